// round 7
// baseline (speedup 1.0000x reference)
#include <cuda_runtime.h>
#include <cuda_bf16.h>
#include <cstdint>

#define N_NODES 100000
#define D 64
#define E_MAX 2400000   // padded CSR: E + up to 7 per node
#define SCAN_BLK 512

// Scratch (__device__ globals). g_buf has an extra ZERO row at index N_NODES:
// never written (CUDA zero-inits .bss), used as the padding gather target.
__device__ __align__(16) float g_buf[(N_NODES + 1) * D];  // g = x @ W^T (unscaled)
__device__ __align__(16) float h1_buf[N_NODES * D];       // layer-1 output
__device__ float dinv_buf[N_NODES + 1];  // [N_NODES] = 0 (dummy)
__device__ int cnt_buf[N_NODES];         // in-degree histogram
__device__ int row_start[N_NODES + 1];   // PADDED CSR row offsets (by dst)
__device__ int cursor_buf[N_NODES];      // placement cursors
__device__ int csr_src[E_MAX];           // CSR column (src) indices + padding
__device__ int block_sums[(N_NODES + SCAN_BLK - 1) / SCAN_BLK];
__device__ int g_is64;                   // edge_index dtype flag

// ---------------------------------------------------------------------------
// Edge dtype probe: int64 LE values < 2^31 -> every odd 32-bit word is 0.
// ---------------------------------------------------------------------------
__global__ void detect_kernel(const int* __restrict__ w, long long nwords) {
    __shared__ int nz;
    if (threadIdx.x == 0) nz = 0;
    __syncthreads();
    int local = 0;
    for (int i = threadIdx.x; i < 2048; i += 256) {
        long long idx = 2LL * i + 1;
        if (idx < nwords && w[idx] != 0) local = 1;
    }
    if (local) atomicAdd(&nz, 1);
    __syncthreads();
    if (threadIdx.x == 0) g_is64 = (nz == 0) ? 1 : 0;
}

__device__ __forceinline__ int edge_idx(const void* __restrict__ ei, long long pos) {
    if (g_is64) return (int)((const long long*)ei)[pos];
    return ((const int*)ei)[pos];
}

// ---------------------------------------------------------------------------
// CSR build: histogram -> padded exclusive scan -> placement -> padding
// ---------------------------------------------------------------------------
__global__ void hist_zero_kernel() {
    int i = blockIdx.x * blockDim.x + threadIdx.x;
    if (i < N_NODES) cnt_buf[i] = 0;
}

__global__ void hist_kernel(const void* __restrict__ ei, int E) {
    int e = blockIdx.x * blockDim.x + threadIdx.x;
    if (e < E) atomicAdd(&cnt_buf[edge_idx(ei, (long long)E + e)], 1);
}

// Scan over PADDED counts ((cnt+7)&~7).
__global__ __launch_bounds__(SCAN_BLK) void scan_block_kernel() {
    __shared__ int s[SCAN_BLK];
    int i = blockIdx.x * SCAN_BLK + threadIdx.x;
    int v = 0;
    if (i < N_NODES) v = (cnt_buf[i] + 7) & ~7;
    s[threadIdx.x] = v;
    __syncthreads();
#pragma unroll
    for (int off = 1; off < SCAN_BLK; off <<= 1) {
        int t = (threadIdx.x >= off) ? s[threadIdx.x - off] : 0;
        __syncthreads();
        s[threadIdx.x] += t;
        __syncthreads();
    }
    if (i < N_NODES) row_start[i] = s[threadIdx.x] - v;  // exclusive
    if (threadIdx.x == SCAN_BLK - 1) block_sums[blockIdx.x] = s[threadIdx.x];
}

__global__ __launch_bounds__(SCAN_BLK) void scan_tops_kernel(int nb) {
    __shared__ int s[SCAN_BLK];
    int v = (threadIdx.x < nb) ? block_sums[threadIdx.x] : 0;
    s[threadIdx.x] = v;
    __syncthreads();
#pragma unroll
    for (int off = 1; off < SCAN_BLK; off <<= 1) {
        int t = (threadIdx.x >= off) ? s[threadIdx.x - off] : 0;
        __syncthreads();
        s[threadIdx.x] += t;
        __syncthreads();
    }
    if (threadIdx.x < nb) block_sums[threadIdx.x] = s[threadIdx.x] - v;
}

__global__ void scan_add_kernel() {
    int i = blockIdx.x * blockDim.x + threadIdx.x;
    if (i < N_NODES) {
        int r = row_start[i] + block_sums[i / SCAN_BLK];
        row_start[i] = r;
        cursor_buf[i] = r;
        int c = cnt_buf[i];
        dinv_buf[i] = rsqrtf((float)c + 1.0f);  // deg + self loop
        if (i == N_NODES - 1) row_start[N_NODES] = r + ((c + 7) & ~7);
    }
    if (i == 0) dinv_buf[N_NODES] = 0.0f;  // dummy row weight
}

__global__ void place_kernel(const void* __restrict__ ei, int E) {
    int e = blockIdx.x * blockDim.x + threadIdx.x;
    if (e < E) {
        int s = edge_idx(ei, e);
        int d = edge_idx(ei, (long long)E + e);
        int pos = atomicAdd(&cursor_buf[d], 1);
        csr_src[pos] = s;
    }
}

// Fill padding slots with the dummy node index (zero row, dinv=0).
__global__ void pad_kernel() {
    int i = blockIdx.x * blockDim.x + threadIdx.x;
    if (i < N_NODES) {
        int p = cursor_buf[i];
        int end = row_start[i + 1];
        for (; p < end; p++) csr_src[p] = N_NODES;
    }
}

// ---------------------------------------------------------------------------
// GEMM: g[row] = x[row] @ W^T  (dinv scaling deferred to pull).
// ---------------------------------------------------------------------------
__global__ __launch_bounds__(256) void gemm_kernel(
    const float* __restrict__ x, const float* __restrict__ W) {
    __shared__ float4 xs[64 * 17];
    __shared__ float4 Ws[64 * 17];

    int tid = threadIdx.x;
    int rowBase = blockIdx.x * 64;

    const float4* W4 = (const float4*)W;
    for (int i = tid; i < 1024; i += 256) {
        int j = i >> 4, kk = i & 15;
        Ws[j * 17 + kk] = W4[i];
    }
    const float4* x4 = (const float4*)x;
    for (int i = tid; i < 1024; i += 256) {
        int r = i >> 4, kk = i & 15;
        if (rowBase + r < N_NODES)
            xs[r * 17 + kk] = x4[(size_t)(rowBase + r) * 16 + kk];
    }
    __syncthreads();

    int tx = tid & 15;
    int ty = tid >> 4;

    float acc[4][4];
#pragma unroll
    for (int i = 0; i < 4; i++)
#pragma unroll
        for (int j = 0; j < 4; j++) acc[i][j] = 0.0f;

#pragma unroll
    for (int kk = 0; kk < 16; kk++) {
        float4 xv[4], wv[4];
#pragma unroll
        for (int l = 0; l < 4; l++) xv[l] = xs[(ty * 4 + l) * 17 + kk];
#pragma unroll
        for (int l = 0; l < 4; l++) wv[l] = Ws[(tx * 4 + l) * 17 + kk];
#pragma unroll
        for (int i = 0; i < 4; i++)
#pragma unroll
            for (int j = 0; j < 4; j++) {
                acc[i][j] = fmaf(xv[i].x, wv[j].x, acc[i][j]);
                acc[i][j] = fmaf(xv[i].y, wv[j].y, acc[i][j]);
                acc[i][j] = fmaf(xv[i].z, wv[j].z, acc[i][j]);
                acc[i][j] = fmaf(xv[i].w, wv[j].w, acc[i][j]);
            }
    }

#pragma unroll
    for (int i = 0; i < 4; i++) {
        int row = rowBase + ty * 4 + i;
        if (row < N_NODES) {
            float4 v;
            v.x = acc[i][0];
            v.y = acc[i][1];
            v.z = acc[i][2];
            v.w = acc[i][3];
            ((float4*)g_buf)[(size_t)row * 16 + tx] = v;
        }
    }
}

// ---------------------------------------------------------------------------
// Pull + fused normalization + bias. 16 threads per dst node (one float4
// each). Rows padded to multiples of 8 -> inner loop is 8 UNCONDITIONAL
// gather-FMAs; padding slots hit the hot zero row with weight 0.
// out[d] = dinv[d] * ( sum_s dinv[s]*g[s] + dinv[d]*g[d] ) + b
// ---------------------------------------------------------------------------
__global__ __launch_bounds__(256) void pull_kernel(
    const float* __restrict__ b, float* __restrict__ out) {
    int gid = blockIdx.x * blockDim.x + threadIdx.x;
    int node = gid >> 4;
    if (node >= N_NODES) return;
    int q = gid & 15;

    const float4* g4 = (const float4*)g_buf;
    int beg = row_start[node];
    int end = row_start[node + 1];
    float dself = dinv_buf[node];

    // self-loop seed: dinv[d] * g[d]
    float4 sv = g4[(size_t)node * 16 + q];
    float4 acc;
    acc.x = dself * sv.x;
    acc.y = dself * sv.y;
    acc.z = dself * sv.z;
    acc.w = dself * sv.w;

    for (int e = beg; e < end; e += 8) {
        int p = e + (q & 7);          // lanes q and q+8 load the same slot
        int idx = csr_src[p];         // always valid (padded)
        float w = dinv_buf[idx];      // dummy -> 0
#pragma unroll
        for (int k = 0; k < 8; k++) {
            int s = __shfl_sync(0xffffffffu, idx, k, 8);
            float ws = __shfl_sync(0xffffffffu, w, k, 8);
            float4 v = g4[(size_t)s * 16 + q];
            acc.x = fmaf(v.x, ws, acc.x);
            acc.y = fmaf(v.y, ws, acc.y);
            acc.z = fmaf(v.z, ws, acc.z);
            acc.w = fmaf(v.w, ws, acc.w);
        }
    }

    float4 bb = ((const float4*)b)[q];
    float4 o;
    o.x = fmaf(dself, acc.x, bb.x);
    o.y = fmaf(dself, acc.y, bb.y);
    o.z = fmaf(dself, acc.z, bb.z);
    o.w = fmaf(dself, acc.w, bb.w);
    ((float4*)out)[gid] = o;
}

// ---------------------------------------------------------------------------
extern "C" void kernel_launch(void* const* d_in, const int* in_sizes, int n_in,
                              void* d_out, int out_size) {
    const float* x = (const float*)d_in[0];
    const void* ei = d_in[1];
    const float* W1 = (const float*)d_in[2];
    const float* b1 = (const float*)d_in[3];
    const float* W2 = (const float*)d_in[4];
    const float* b2 = (const float*)d_in[5];
    float* out = (float*)d_out;

    int E = in_sizes[1] / 2;

    int nThreads = 256;
    int nodeBlocks = (N_NODES + nThreads - 1) / nThreads;
    int edgeBlocks = (E + nThreads - 1) / nThreads;
    int gemmBlocks = (N_NODES + 63) / 64;
    int pullBlocks = (N_NODES * 16 + nThreads - 1) / nThreads;
    int scanBlocks = (N_NODES + SCAN_BLK - 1) / SCAN_BLK;

    // Launch order chosen so launch #4 = hist_kernel (ncu window lands there).
    gemm_kernel<<<gemmBlocks, nThreads>>>(x, W1);              // 1 (independent of CSR)
    detect_kernel<<<1, 256>>>((const int*)ei, (long long)E * 2);  // 2
    hist_zero_kernel<<<nodeBlocks, nThreads>>>();              // 3
    hist_kernel<<<edgeBlocks, nThreads>>>(ei, E);              // 4  <-- profiled
    scan_block_kernel<<<scanBlocks, SCAN_BLK>>>();             // 5
    scan_tops_kernel<<<1, SCAN_BLK>>>(scanBlocks);             // 6
    scan_add_kernel<<<nodeBlocks, nThreads>>>();               // 7
    place_kernel<<<edgeBlocks, nThreads>>>(ei, E);             // 8
    pad_kernel<<<nodeBlocks, nThreads>>>();                    // 9

    // Layer 1 aggregation
    pull_kernel<<<pullBlocks, nThreads>>>(b1, h1_buf);         // 10

    // Layer 2
    gemm_kernel<<<gemmBlocks, nThreads>>>(h1_buf, W2);         // 11
    pull_kernel<<<pullBlocks, nThreads>>>(b2, out);            // 12
}

// round 9
// speedup vs baseline: 1.0906x; 1.0906x over previous
#include <cuda_runtime.h>
#include <cuda_bf16.h>
#include <cstdint>

#define N_NODES 100000
#define D 64
#define E_MAX 1700000
#define SCAN_BLK 512

// Scratch (__device__ globals: the sanctioned allocation-free path).
__device__ __align__(16) float g_buf[N_NODES * D];   // g = (x @ W^T) * dinv[row]
__device__ __align__(16) float h1_buf[N_NODES * D];  // layer-1 output
__device__ float dinv_buf[N_NODES];
__device__ int cnt_buf[N_NODES];       // in-degree histogram
__device__ int row_start[N_NODES + 1]; // CSR row offsets (by dst)
__device__ int cursor_buf[N_NODES];    // placement cursors
__device__ int csr_src[E_MAX];         // CSR column (src) indices
__device__ int block_sums[(N_NODES + SCAN_BLK - 1) / SCAN_BLK];
__device__ int g_is64;                 // edge_index dtype flag

// ---------------------------------------------------------------------------
// Edge dtype probe: int64 LE values < 2^31 -> every odd 32-bit word is 0.
// ---------------------------------------------------------------------------
__global__ void detect_kernel(const int* __restrict__ w, long long nwords) {
    __shared__ int nz;
    if (threadIdx.x == 0) nz = 0;
    __syncthreads();
    int local = 0;
    for (int i = threadIdx.x; i < 2048; i += 256) {
        long long idx = 2LL * i + 1;
        if (idx < nwords && w[idx] != 0) local = 1;
    }
    if (local) atomicAdd(&nz, 1);
    __syncthreads();
    if (threadIdx.x == 0) g_is64 = (nz == 0) ? 1 : 0;
}

__device__ __forceinline__ int edge_idx(const void* __restrict__ ei, long long pos) {
    if (g_is64) return (int)((const long long*)ei)[pos];
    return ((const int*)ei)[pos];
}

// ---------------------------------------------------------------------------
// CSR build: histogram -> exclusive scan -> placement
// ---------------------------------------------------------------------------
__global__ void hist_zero_kernel() {
    int i = blockIdx.x * blockDim.x + threadIdx.x;
    if (i < N_NODES) cnt_buf[i] = 0;
}

__global__ void hist_kernel(const void* __restrict__ ei, int E) {
    int e = blockIdx.x * blockDim.x + threadIdx.x;
    if (e < E) atomicAdd(&cnt_buf[edge_idx(ei, (long long)E + e)], 1);
}

__global__ __launch_bounds__(SCAN_BLK) void scan_block_kernel() {
    __shared__ int s[SCAN_BLK];
    int i = blockIdx.x * SCAN_BLK + threadIdx.x;
    int v = (i < N_NODES) ? cnt_buf[i] : 0;
    s[threadIdx.x] = v;
    __syncthreads();
#pragma unroll
    for (int off = 1; off < SCAN_BLK; off <<= 1) {
        int t = (threadIdx.x >= off) ? s[threadIdx.x - off] : 0;
        __syncthreads();
        s[threadIdx.x] += t;
        __syncthreads();
    }
    if (i < N_NODES) row_start[i] = s[threadIdx.x] - v;  // exclusive
    if (threadIdx.x == SCAN_BLK - 1) block_sums[blockIdx.x] = s[threadIdx.x];
}

__global__ __launch_bounds__(SCAN_BLK) void scan_tops_kernel(int nb) {
    __shared__ int s[SCAN_BLK];
    int v = (threadIdx.x < nb) ? block_sums[threadIdx.x] : 0;
    s[threadIdx.x] = v;
    __syncthreads();
#pragma unroll
    for (int off = 1; off < SCAN_BLK; off <<= 1) {
        int t = (threadIdx.x >= off) ? s[threadIdx.x - off] : 0;
        __syncthreads();
        s[threadIdx.x] += t;
        __syncthreads();
    }
    if (threadIdx.x < nb) block_sums[threadIdx.x] = s[threadIdx.x] - v;
}

__global__ void scan_add_kernel(int E) {
    int i = blockIdx.x * blockDim.x + threadIdx.x;
    if (i < N_NODES) {
        int r = row_start[i] + block_sums[i / SCAN_BLK];
        row_start[i] = r;
        cursor_buf[i] = r;
        dinv_buf[i] = rsqrtf((float)cnt_buf[i] + 1.0f);  // deg + self loop
    }
    if (i == 0) row_start[N_NODES] = E;
}

__global__ void place_kernel(const void* __restrict__ ei, int E) {
    int e = blockIdx.x * blockDim.x + threadIdx.x;
    if (e < E) {
        int s = edge_idx(ei, e);
        int d = edge_idx(ei, (long long)E + e);
        int pos = atomicAdd(&cursor_buf[d], 1);
        csr_src[pos] = s;
    }
}

// ---------------------------------------------------------------------------
// GEMM: g[row] = (x[row] @ W^T) * dinv[row].
// ---------------------------------------------------------------------------
__global__ __launch_bounds__(256) void gemm_scale_kernel(
    const float* __restrict__ x, const float* __restrict__ W) {
    __shared__ float4 xs[64 * 17];
    __shared__ float4 Ws[64 * 17];

    int tid = threadIdx.x;
    int rowBase = blockIdx.x * 64;

    const float4* W4 = (const float4*)W;
    for (int i = tid; i < 1024; i += 256) {
        int j = i >> 4, kk = i & 15;
        Ws[j * 17 + kk] = W4[i];
    }
    const float4* x4 = (const float4*)x;
    for (int i = tid; i < 1024; i += 256) {
        int r = i >> 4, kk = i & 15;
        if (rowBase + r < N_NODES)
            xs[r * 17 + kk] = x4[(size_t)(rowBase + r) * 16 + kk];
    }
    __syncthreads();

    int tx = tid & 15;
    int ty = tid >> 4;

    float acc[4][4];
#pragma unroll
    for (int i = 0; i < 4; i++)
#pragma unroll
        for (int j = 0; j < 4; j++) acc[i][j] = 0.0f;

#pragma unroll
    for (int kk = 0; kk < 16; kk++) {
        float4 xv[4], wv[4];
#pragma unroll
        for (int l = 0; l < 4; l++) xv[l] = xs[(ty * 4 + l) * 17 + kk];
#pragma unroll
        for (int l = 0; l < 4; l++) wv[l] = Ws[(tx * 4 + l) * 17 + kk];
#pragma unroll
        for (int i = 0; i < 4; i++)
#pragma unroll
            for (int j = 0; j < 4; j++) {
                acc[i][j] = fmaf(xv[i].x, wv[j].x, acc[i][j]);
                acc[i][j] = fmaf(xv[i].y, wv[j].y, acc[i][j]);
                acc[i][j] = fmaf(xv[i].z, wv[j].z, acc[i][j]);
                acc[i][j] = fmaf(xv[i].w, wv[j].w, acc[i][j]);
            }
    }

#pragma unroll
    for (int i = 0; i < 4; i++) {
        int row = rowBase + ty * 4 + i;
        if (row < N_NODES) {
            float di = dinv_buf[row];
            float4 v;
            v.x = acc[i][0] * di;
            v.y = acc[i][1] * di;
            v.z = acc[i][2] * di;
            v.w = acc[i][3] * di;
            ((float4*)g_buf)[(size_t)row * 16 + tx] = v;
        }
    }
}

// ---------------------------------------------------------------------------
// Pull aggregation + fused finalize (r5-best form).
// 16 threads per dst node; each owns one float4 of the 64-float row.
// nodeCap: allows a partial diagnostic launch over the first K nodes.
// ---------------------------------------------------------------------------
__global__ __launch_bounds__(256) void pull_kernel(
    const float* __restrict__ b, float* __restrict__ out, int nodeCap) {
    int gid = blockIdx.x * blockDim.x + threadIdx.x;
    int node = gid >> 4;
    if (node >= nodeCap) return;
    int q = gid & 15;

    const float4* g4 = (const float4*)g_buf;
    int beg = row_start[node];
    int end = row_start[node + 1];

    // self loop seed
    float4 acc = g4[(size_t)node * 16 + q];

    int e = beg;
    for (; e + 1 < end; e += 2) {
        int s0 = csr_src[e];
        int s1 = csr_src[e + 1];
        float4 v0 = g4[(size_t)s0 * 16 + q];
        float4 v1 = g4[(size_t)s1 * 16 + q];
        acc.x += v0.x + v1.x;
        acc.y += v0.y + v1.y;
        acc.z += v0.z + v1.z;
        acc.w += v0.w + v1.w;
    }
    if (e < end) {
        int s0 = csr_src[e];
        float4 v0 = g4[(size_t)s0 * 16 + q];
        acc.x += v0.x;
        acc.y += v0.y;
        acc.z += v0.z;
        acc.w += v0.w;
    }

    float di = dinv_buf[node];
    float4 bb = ((const float4*)b)[q];
    float4 o;
    o.x = fmaf(di, acc.x, bb.x);
    o.y = fmaf(di, acc.y, bb.y);
    o.z = fmaf(di, acc.z, bb.z);
    o.w = fmaf(di, acc.w, bb.w);
    ((float4*)out)[gid] = o;
}

// ---------------------------------------------------------------------------
extern "C" void kernel_launch(void* const* d_in, const int* in_sizes, int n_in,
                              void* d_out, int out_size) {
    const float* x = (const float*)d_in[0];
    const void* ei = d_in[1];
    const float* W1 = (const float*)d_in[2];
    const float* b1 = (const float*)d_in[3];
    const float* W2 = (const float*)d_in[4];
    const float* b2 = (const float*)d_in[5];
    float* out = (float*)d_out;

    int E = in_sizes[1] / 2;

    int nThreads = 256;
    int nodeBlocks = (N_NODES + nThreads - 1) / nThreads;
    int edgeBlocks = (E + nThreads - 1) / nThreads;
    int gemmBlocks = (N_NODES + 63) / 64;
    int pullBlocks = (N_NODES * 16 + nThreads - 1) / nThreads;
    int scanBlocks = (N_NODES + SCAN_BLK - 1) / SCAN_BLK;

    // Diagnostic duplicate pull at launch #4 (ncu window): partial grid
    // (1024 blocks = 16384 nodes) over the PREVIOUS call's CSR/g state
    // (zeros on the very first call -> rows empty -> harmless). Writes
    // h1_buf, which the real pull1 below fully overwrites -> output
    // deterministic. Extrapolate: full pull dur ~= dup dur * 6250/1024.
    detect_kernel<<<1, 256>>>((const int*)ei, (long long)E * 2);   // 1
    hist_zero_kernel<<<nodeBlocks, nThreads>>>();                  // 2
    hist_kernel<<<edgeBlocks, nThreads>>>(ei, E);                  // 3
    pull_kernel<<<1024, nThreads>>>(b1, h1_buf, 16384);            // 4 <-- profiled
    scan_block_kernel<<<scanBlocks, SCAN_BLK>>>();                 // 5
    scan_tops_kernel<<<1, SCAN_BLK>>>(scanBlocks);                 // 6
    scan_add_kernel<<<nodeBlocks, nThreads>>>(E);                  // 7
    place_kernel<<<edgeBlocks, nThreads>>>(ei, E);                 // 8

    // Layer 1
    gemm_scale_kernel<<<gemmBlocks, nThreads>>>(x, W1);            // 9
    pull_kernel<<<pullBlocks, nThreads>>>(b1, h1_buf, N_NODES);    // 10

    // Layer 2
    gemm_scale_kernel<<<gemmBlocks, nThreads>>>(h1_buf, W2);       // 11
    pull_kernel<<<pullBlocks, nThreads>>>(b2, out, N_NODES);       // 12
}

// round 10
// speedup vs baseline: 1.0946x; 1.0037x over previous
#include <cuda_runtime.h>
#include <cuda_bf16.h>
#include <cstdint>

#define N_NODES 100000
#define D 64
#define E_MAX 1700000
#define SCAN_BLK 512

// Scratch (__device__ globals: the sanctioned allocation-free path).
__device__ __align__(16) float g_buf[N_NODES * D];   // g = (x @ W^T) * dinv[row]
__device__ __align__(16) float h1_buf[N_NODES * D];  // layer-1 output
__device__ float dinv_buf[N_NODES];
__device__ int cnt_buf[N_NODES];       // in-degree histogram (re-zeroed by scan_finish)
__device__ int row_start[N_NODES + 1]; // CSR row offsets (by dst)
__device__ int cursor_buf[N_NODES];    // placement cursors
__device__ int csr_src[E_MAX];         // CSR column (src) indices
__device__ int block_sums[(N_NODES + SCAN_BLK - 1) / SCAN_BLK];

// ---------------------------------------------------------------------------
// Histogram of in-degrees. cnt_buf is zero on entry (.bss on call 1,
// re-zeroed by scan_finish_kernel on every call thereafter).
// Edge buffer is int32 (proven: int64 reads OOB-crashed in round 3).
// ---------------------------------------------------------------------------
__global__ void hist_kernel(const int* __restrict__ ei, int E) {
    int e = blockIdx.x * blockDim.x + threadIdx.x;
    if (e < E) atomicAdd(&cnt_buf[ei[E + e]], 1);
}

// Per-512-block exclusive scan of cnt_buf; block totals to block_sums.
__global__ __launch_bounds__(SCAN_BLK) void scan_block_kernel() {
    __shared__ int s[SCAN_BLK];
    int i = blockIdx.x * SCAN_BLK + threadIdx.x;
    int v = (i < N_NODES) ? cnt_buf[i] : 0;
    s[threadIdx.x] = v;
    __syncthreads();
#pragma unroll
    for (int off = 1; off < SCAN_BLK; off <<= 1) {
        int t = (threadIdx.x >= off) ? s[threadIdx.x - off] : 0;
        __syncthreads();
        s[threadIdx.x] += t;
        __syncthreads();
    }
    if (i < N_NODES) row_start[i] = s[threadIdx.x] - v;  // local exclusive
    if (threadIdx.x == SCAN_BLK - 1) block_sums[blockIdx.x] = s[threadIdx.x];
}

// Fused: redundant in-block scan of block_sums (nb <= 256) + global offset
// add + cursor init + dinv + cnt re-zero + sentinel.
__global__ __launch_bounds__(256) void scan_finish_kernel(int E, int nb) {
    __shared__ int s[256];
    __shared__ int excl[256];
    int v = (threadIdx.x < nb) ? block_sums[threadIdx.x] : 0;
    s[threadIdx.x] = v;
    __syncthreads();
#pragma unroll
    for (int off = 1; off < 256; off <<= 1) {
        int t = (threadIdx.x >= off) ? s[threadIdx.x - off] : 0;
        __syncthreads();
        s[threadIdx.x] += t;
        __syncthreads();
    }
    excl[threadIdx.x] = s[threadIdx.x] - v;  // exclusive prefix per segment
    __syncthreads();

    int i = blockIdx.x * blockDim.x + threadIdx.x;
    if (i < N_NODES) {
        int r = row_start[i] + excl[i / SCAN_BLK];
        row_start[i] = r;
        cursor_buf[i] = r;
        dinv_buf[i] = rsqrtf((float)cnt_buf[i] + 1.0f);  // deg + self loop
        cnt_buf[i] = 0;  // maintain zero invariant for next call
    }
    if (i == 0) row_start[N_NODES] = E;
}

__global__ void place_kernel(const int* __restrict__ ei, int E) {
    int e = blockIdx.x * blockDim.x + threadIdx.x;
    if (e < E) {
        int s = ei[e];
        int d = ei[E + e];
        int pos = atomicAdd(&cursor_buf[d], 1);
        csr_src[pos] = s;
    }
}

// ---------------------------------------------------------------------------
// GEMM: g[row] = (x[row] @ W^T) * dinv[row]. (r5-proven form)
// ---------------------------------------------------------------------------
__global__ __launch_bounds__(256) void gemm_scale_kernel(
    const float* __restrict__ x, const float* __restrict__ W) {
    __shared__ float4 xs[64 * 17];
    __shared__ float4 Ws[64 * 17];

    int tid = threadIdx.x;
    int rowBase = blockIdx.x * 64;

    const float4* W4 = (const float4*)W;
    for (int i = tid; i < 1024; i += 256) {
        int j = i >> 4, kk = i & 15;
        Ws[j * 17 + kk] = W4[i];
    }
    const float4* x4 = (const float4*)x;
    for (int i = tid; i < 1024; i += 256) {
        int r = i >> 4, kk = i & 15;
        if (rowBase + r < N_NODES)
            xs[r * 17 + kk] = x4[(size_t)(rowBase + r) * 16 + kk];
    }
    __syncthreads();

    int tx = tid & 15;
    int ty = tid >> 4;

    float acc[4][4];
#pragma unroll
    for (int i = 0; i < 4; i++)
#pragma unroll
        for (int j = 0; j < 4; j++) acc[i][j] = 0.0f;

#pragma unroll
    for (int kk = 0; kk < 16; kk++) {
        float4 xv[4], wv[4];
#pragma unroll
        for (int l = 0; l < 4; l++) xv[l] = xs[(ty * 4 + l) * 17 + kk];
#pragma unroll
        for (int l = 0; l < 4; l++) wv[l] = Ws[(tx * 4 + l) * 17 + kk];
#pragma unroll
        for (int i = 0; i < 4; i++)
#pragma unroll
            for (int j = 0; j < 4; j++) {
                acc[i][j] = fmaf(xv[i].x, wv[j].x, acc[i][j]);
                acc[i][j] = fmaf(xv[i].y, wv[j].y, acc[i][j]);
                acc[i][j] = fmaf(xv[i].z, wv[j].z, acc[i][j]);
                acc[i][j] = fmaf(xv[i].w, wv[j].w, acc[i][j]);
            }
    }

#pragma unroll
    for (int i = 0; i < 4; i++) {
        int row = rowBase + ty * 4 + i;
        if (row < N_NODES) {
            float di = dinv_buf[row];
            float4 v;
            v.x = acc[i][0] * di;
            v.y = acc[i][1] * di;
            v.z = acc[i][2] * di;
            v.w = acc[i][3] * di;
            ((float4*)g_buf)[(size_t)row * 16 + tx] = v;
        }
    }
}

// ---------------------------------------------------------------------------
// Pull aggregation + fused finalize (r5-proven form).
// 16 threads per dst node; each owns one float4 of the 64-float row.
// ---------------------------------------------------------------------------
__global__ __launch_bounds__(256) void pull_kernel(
    const float* __restrict__ b, float* __restrict__ out) {
    int gid = blockIdx.x * blockDim.x + threadIdx.x;
    int node = gid >> 4;
    if (node >= N_NODES) return;
    int q = gid & 15;

    const float4* g4 = (const float4*)g_buf;
    int beg = row_start[node];
    int end = row_start[node + 1];

    // self loop seed
    float4 acc = g4[(size_t)node * 16 + q];

    int e = beg;
    for (; e + 1 < end; e += 2) {
        int s0 = csr_src[e];
        int s1 = csr_src[e + 1];
        float4 v0 = g4[(size_t)s0 * 16 + q];
        float4 v1 = g4[(size_t)s1 * 16 + q];
        acc.x += v0.x + v1.x;
        acc.y += v0.y + v1.y;
        acc.z += v0.z + v1.z;
        acc.w += v0.w + v1.w;
    }
    if (e < end) {
        int s0 = csr_src[e];
        float4 v0 = g4[(size_t)s0 * 16 + q];
        acc.x += v0.x;
        acc.y += v0.y;
        acc.z += v0.z;
        acc.w += v0.w;
    }

    float di = dinv_buf[node];
    float4 bb = ((const float4*)b)[q];
    float4 o;
    o.x = fmaf(di, acc.x, bb.x);
    o.y = fmaf(di, acc.y, bb.y);
    o.z = fmaf(di, acc.z, bb.z);
    o.w = fmaf(di, acc.w, bb.w);
    ((float4*)out)[gid] = o;
}

// ---------------------------------------------------------------------------
extern "C" void kernel_launch(void* const* d_in, const int* in_sizes, int n_in,
                              void* d_out, int out_size) {
    const float* x = (const float*)d_in[0];
    const int* ei = (const int*)d_in[1];
    const float* W1 = (const float*)d_in[2];
    const float* b1 = (const float*)d_in[3];
    const float* W2 = (const float*)d_in[4];
    const float* b2 = (const float*)d_in[5];
    float* out = (float*)d_out;

    int E = in_sizes[1] / 2;

    int nThreads = 256;
    int nodeBlocks = (N_NODES + nThreads - 1) / nThreads;
    int edgeBlocks = (E + nThreads - 1) / nThreads;
    int gemmBlocks = (N_NODES + 63) / 64;
    int pullBlocks = (N_NODES * 16 + nThreads - 1) / nThreads;
    int scanBlocks = (N_NODES + SCAN_BLK - 1) / SCAN_BLK;  // 196 <= 256

    hist_kernel<<<edgeBlocks, nThreads>>>(ei, E);          // 1
    scan_block_kernel<<<scanBlocks, SCAN_BLK>>>();         // 2
    scan_finish_kernel<<<nodeBlocks, nThreads>>>(E, scanBlocks);  // 3
    place_kernel<<<edgeBlocks, nThreads>>>(ei, E);         // 4  <-- ncu window

    // Layer 1
    gemm_scale_kernel<<<gemmBlocks, nThreads>>>(x, W1);    // 5
    pull_kernel<<<pullBlocks, nThreads>>>(b1, h1_buf);     // 6

    // Layer 2
    gemm_scale_kernel<<<gemmBlocks, nThreads>>>(h1_buf, W2);  // 7
    pull_kernel<<<pullBlocks, nThreads>>>(b2, out);        // 8
}

// round 12
// speedup vs baseline: 1.2484x; 1.1405x over previous
#include <cuda_runtime.h>
#include <cuda_bf16.h>
#include <cstdint>

#define N_NODES 100000
#define D 64
#define E_MAX 1700000
#define SCAN_BLK 512
#define KSTRIDE 68  // floats per k-row in smem; 68*4=272B, 16B-aligned, odd %8 quads

// Scratch (__device__ globals: the sanctioned allocation-free path).
__device__ __align__(16) float g_buf[N_NODES * D];   // g = (x @ W^T) * dinv[row]
__device__ __align__(16) float h1_buf[N_NODES * D];  // layer-1 output
__device__ float dinv_buf[N_NODES];
__device__ int cnt_buf[N_NODES];       // in-degree histogram (re-zeroed by scan_finish)
__device__ int row_start[N_NODES + 1]; // CSR row offsets (by dst)
__device__ int cursor_buf[N_NODES];    // placement cursors
__device__ int csr_src[E_MAX];         // CSR column (src) indices
__device__ int block_sums[(N_NODES + SCAN_BLK - 1) / SCAN_BLK];

// f32x2 packed helpers (Blackwell FFMA2 path — PTX only)
__device__ __forceinline__ void ffma2(unsigned long long& acc,
                                      unsigned long long a, unsigned long long b) {
    asm("fma.rn.f32x2 %0, %1, %2, %3;" : "=l"(acc) : "l"(a), "l"(b), "l"(acc));
}
__device__ __forceinline__ unsigned long long pack2(float lo, float hi) {
    unsigned long long r;
    asm("mov.b64 %0, {%1, %2};" : "=l"(r) : "f"(lo), "f"(hi));
    return r;
}
__device__ __forceinline__ void unpack2(unsigned long long v, float& lo, float& hi) {
    asm("mov.b64 {%0, %1}, %2;" : "=f"(lo), "=f"(hi) : "l"(v));
}

// ---------------------------------------------------------------------------
// Histogram of in-degrees. cnt_buf zero on entry (.bss call 1, re-zeroed
// by scan_finish each call). Edge buffer is int32 (proven in round 3/4).
// ---------------------------------------------------------------------------
__global__ void hist_kernel(const int* __restrict__ ei, int E) {
    int e = blockIdx.x * blockDim.x + threadIdx.x;
    if (e < E) atomicAdd(&cnt_buf[ei[E + e]], 1);
}

__global__ __launch_bounds__(SCAN_BLK) void scan_block_kernel() {
    __shared__ int s[SCAN_BLK];
    int i = blockIdx.x * SCAN_BLK + threadIdx.x;
    int v = (i < N_NODES) ? cnt_buf[i] : 0;
    s[threadIdx.x] = v;
    __syncthreads();
#pragma unroll
    for (int off = 1; off < SCAN_BLK; off <<= 1) {
        int t = (threadIdx.x >= off) ? s[threadIdx.x - off] : 0;
        __syncthreads();
        s[threadIdx.x] += t;
        __syncthreads();
    }
    if (i < N_NODES) row_start[i] = s[threadIdx.x] - v;
    if (threadIdx.x == SCAN_BLK - 1) block_sums[blockIdx.x] = s[threadIdx.x];
}

__global__ __launch_bounds__(256) void scan_finish_kernel(int E, int nb) {
    __shared__ int s[256];
    __shared__ int excl[256];
    int v = (threadIdx.x < nb) ? block_sums[threadIdx.x] : 0;
    s[threadIdx.x] = v;
    __syncthreads();
#pragma unroll
    for (int off = 1; off < 256; off <<= 1) {
        int t = (threadIdx.x >= off) ? s[threadIdx.x - off] : 0;
        __syncthreads();
        s[threadIdx.x] += t;
        __syncthreads();
    }
    excl[threadIdx.x] = s[threadIdx.x] - v;
    __syncthreads();

    int i = blockIdx.x * blockDim.x + threadIdx.x;
    if (i < N_NODES) {
        int r = row_start[i] + excl[i / SCAN_BLK];
        row_start[i] = r;
        cursor_buf[i] = r;
        dinv_buf[i] = rsqrtf((float)cnt_buf[i] + 1.0f);  // deg + self loop
        cnt_buf[i] = 0;
    }
    if (i == 0) row_start[N_NODES] = E;
}

__global__ void place_kernel(const int* __restrict__ ei, int E) {
    int e = blockIdx.x * blockDim.x + threadIdx.x;
    if (e < E) {
        int s = ei[e];
        int d = ei[E + e];
        int pos = atomicAdd(&cursor_buf[d], 1);
        csr_src[pos] = s;
    }
}

// ---------------------------------------------------------------------------
// GEMM: g[row] = (x[row] @ W^T) * dinv[row].
// Conflict-free rewrite: tiles stored k-major [k][col], stride KSTRIDE,
// XOR swizzle on the float4-column index (j4 ^ (k>>2)&7):
//  - MMA wv read  = 16 lanes -> contiguous 256B LDS.128, conflict-free
//  - store phase  = 2-way conflicts (was 8-way on the old layout)
// Inner loop: scalar k outer product via packed fma.rn.f32x2 (FFMA2).
// ---------------------------------------------------------------------------
__global__ __launch_bounds__(256) void gemm_scale_kernel(
    const float* __restrict__ x, const float* __restrict__ W) {
    __shared__ __align__(16) float Wt[64 * KSTRIDE];  // [k][j], swizzled
    __shared__ __align__(16) float Xt[64 * KSTRIDE];  // [k][r], swizzled

    int tid = threadIdx.x;
    int rowBase = blockIdx.x * 64;

    const float4* W4 = (const float4*)W;
    const float4* x4 = (const float4*)x;
    for (int i = tid; i < 1024; i += 256) {
        int j = i >> 4;    // row of W (= output col) / row of x tile
        int kk = i & 15;   // k float4 group
        int j4 = j >> 2, jr = j & 3;
        float4 w = W4[i];
#pragma unroll
        for (int c = 0; c < 4; c++) {
            int k = 4 * kk + c;
            int col = ((j4 ^ (kk & 7)) << 2) + jr;
            float wv = (c == 0) ? w.x : (c == 1) ? w.y : (c == 2) ? w.z : w.w;
            Wt[k * KSTRIDE + col] = wv;
        }
        float4 xv = make_float4(0.f, 0.f, 0.f, 0.f);
        if (rowBase + j < N_NODES) xv = x4[(size_t)(rowBase + j) * 16 + kk];
#pragma unroll
        for (int c = 0; c < 4; c++) {
            int k = 4 * kk + c;
            int col = ((j4 ^ (kk & 7)) << 2) + jr;
            float vv = (c == 0) ? xv.x : (c == 1) ? xv.y : (c == 2) ? xv.z : xv.w;
            Xt[k * KSTRIDE + col] = vv;
        }
    }
    __syncthreads();

    int tx = tid & 15;  // output cols 4tx..4tx+3
    int ty = tid >> 4;  // rows 4ty..4ty+3

    unsigned long long acc2[4][2];
#pragma unroll
    for (int i = 0; i < 4; i++) { acc2[i][0] = 0ULL; acc2[i][1] = 0ULL; }

#pragma unroll
    for (int k = 0; k < 64; k++) {
        int f = (k >> 2) & 7;
        // wv: cols 4tx..4tx+3 of W^T row k  (two packed f32x2)
        const ulonglong2 wv2 =
            *(const ulonglong2*)&Wt[k * KSTRIDE + ((tx ^ f) << 2)];
        // xv: rows 4ty..4ty+3 of x tile at k
        const float4 xv = *(const float4*)&Xt[k * KSTRIDE + ((ty ^ f) << 2)];
        float xr[4] = {xv.x, xv.y, xv.z, xv.w};
#pragma unroll
        for (int i = 0; i < 4; i++) {
            unsigned long long xx = pack2(xr[i], xr[i]);
            ffma2(acc2[i][0], xx, wv2.x);
            ffma2(acc2[i][1], xx, wv2.y);
        }
    }

#pragma unroll
    for (int i = 0; i < 4; i++) {
        int row = rowBase + ty * 4 + i;
        if (row < N_NODES) {
            float di = dinv_buf[row];
            float o0, o1, o2, o3;
            unpack2(acc2[i][0], o0, o1);
            unpack2(acc2[i][1], o2, o3);
            float4 v;
            v.x = o0 * di;
            v.y = o1 * di;
            v.z = o2 * di;
            v.w = o3 * di;
            ((float4*)g_buf)[(size_t)row * 16 + tx] = v;
        }
    }
}

// ---------------------------------------------------------------------------
// Pull aggregation + fused finalize (r5-proven form).
// ---------------------------------------------------------------------------
__global__ __launch_bounds__(256) void pull_kernel(
    const float* __restrict__ b, float* __restrict__ out) {
    int gid = blockIdx.x * blockDim.x + threadIdx.x;
    int node = gid >> 4;
    if (node >= N_NODES) return;
    int q = gid & 15;

    const float4* g4 = (const float4*)g_buf;
    int beg = row_start[node];
    int end = row_start[node + 1];

    float4 acc = g4[(size_t)node * 16 + q];  // self loop

    int e = beg;
    for (; e + 1 < end; e += 2) {
        int s0 = csr_src[e];
        int s1 = csr_src[e + 1];
        float4 v0 = g4[(size_t)s0 * 16 + q];
        float4 v1 = g4[(size_t)s1 * 16 + q];
        acc.x += v0.x + v1.x;
        acc.y += v0.y + v1.y;
        acc.z += v0.z + v1.z;
        acc.w += v0.w + v1.w;
    }
    if (e < end) {
        int s0 = csr_src[e];
        float4 v0 = g4[(size_t)s0 * 16 + q];
        acc.x += v0.x;
        acc.y += v0.y;
        acc.z += v0.z;
        acc.w += v0.w;
    }

    float di = dinv_buf[node];
    float4 bb = ((const float4*)b)[q];
    float4 o;
    o.x = fmaf(di, acc.x, bb.x);
    o.y = fmaf(di, acc.y, bb.y);
    o.z = fmaf(di, acc.z, bb.z);
    o.w = fmaf(di, acc.w, bb.w);
    ((float4*)out)[gid] = o;
}

// ---------------------------------------------------------------------------
extern "C" void kernel_launch(void* const* d_in, const int* in_sizes, int n_in,
                              void* d_out, int out_size) {
    const float* x = (const float*)d_in[0];
    const int* ei = (const int*)d_in[1];
    const float* W1 = (const float*)d_in[2];
    const float* b1 = (const float*)d_in[3];
    const float* W2 = (const float*)d_in[4];
    const float* b2 = (const float*)d_in[5];
    float* out = (float*)d_out;

    int E = in_sizes[1] / 2;

    int nThreads = 256;
    int nodeBlocks = (N_NODES + nThreads - 1) / nThreads;
    int edgeBlocks = (E + nThreads - 1) / nThreads;
    int gemmBlocks = (N_NODES + 63) / 64;
    int pullBlocks = (N_NODES * 16 + nThreads - 1) / nThreads;
    int scanBlocks = (N_NODES + SCAN_BLK - 1) / SCAN_BLK;

    hist_kernel<<<edgeBlocks, nThreads>>>(ei, E);                 // 1
    scan_block_kernel<<<scanBlocks, SCAN_BLK>>>();                // 2
    scan_finish_kernel<<<nodeBlocks, nThreads>>>(E, scanBlocks);  // 3
    gemm_scale_kernel<<<gemmBlocks, nThreads>>>(x, W1);           // 4 <-- ncu window
    place_kernel<<<edgeBlocks, nThreads>>>(ei, E);                // 5

    // Layer 1 aggregation
    pull_kernel<<<pullBlocks, nThreads>>>(b1, h1_buf);            // 6

    // Layer 2
    gemm_scale_kernel<<<gemmBlocks, nThreads>>>(h1_buf, W2);      // 7
    pull_kernel<<<pullBlocks, nThreads>>>(b2, out);               // 8
}

// round 13
// speedup vs baseline: 1.2542x; 1.0047x over previous
#include <cuda_runtime.h>
#include <cuda_bf16.h>
#include <cstdint>

#define N_NODES 100000
#define D 64
#define E_MAX 1700000
#define SCAN_BLK 512
#define KSTRIDE 68  // floats per k-row in smem; 68*4=272B, 16B-aligned

// Scratch (__device__ globals: the sanctioned allocation-free path).
__device__ __align__(16) float g_buf[N_NODES * D];   // g = (x @ W^T) * dinv[row]
__device__ __align__(16) float h1_buf[N_NODES * D];  // layer-1 output
__device__ float dinv_buf[N_NODES];
__device__ int cnt_buf[N_NODES];       // in-degree histogram (re-zeroed by scan_finish)
__device__ int row_start[N_NODES + 1]; // CSR row offsets (by dst)
__device__ int cursor_buf[N_NODES];    // placement cursors
__device__ int csr_src[E_MAX];         // CSR column (src) indices
__device__ int block_sums[(N_NODES + SCAN_BLK - 1) / SCAN_BLK];

// f32x2 packed helpers (Blackwell FFMA2 path — PTX only)
__device__ __forceinline__ void ffma2(unsigned long long& acc,
                                      unsigned long long a, unsigned long long b) {
    asm("fma.rn.f32x2 %0, %1, %2, %3;" : "=l"(acc) : "l"(a), "l"(b), "l"(acc));
}
__device__ __forceinline__ unsigned long long pack2(float lo, float hi) {
    unsigned long long r;
    asm("mov.b64 %0, {%1, %2};" : "=l"(r) : "f"(lo), "f"(hi));
    return r;
}
__device__ __forceinline__ void unpack2(unsigned long long v, float& lo, float& hi) {
    asm("mov.b64 {%0, %1}, %2;" : "=f"(lo), "=f"(hi) : "l"(v));
}

// ---------------------------------------------------------------------------
// Histogram of in-degrees. cnt_buf zero on entry (.bss call 1, re-zeroed
// by scan_finish each call). Edge buffer is int32 (proven in rounds 3/4).
// ---------------------------------------------------------------------------
__global__ void hist_kernel(const int* __restrict__ ei, int E) {
    int e = blockIdx.x * blockDim.x + threadIdx.x;
    if (e < E) atomicAdd(&cnt_buf[ei[E + e]], 1);
}

__global__ __launch_bounds__(SCAN_BLK) void scan_block_kernel() {
    __shared__ int s[SCAN_BLK];
    int i = blockIdx.x * SCAN_BLK + threadIdx.x;
    int v = (i < N_NODES) ? cnt_buf[i] : 0;
    s[threadIdx.x] = v;
    __syncthreads();
#pragma unroll
    for (int off = 1; off < SCAN_BLK; off <<= 1) {
        int t = (threadIdx.x >= off) ? s[threadIdx.x - off] : 0;
        __syncthreads();
        s[threadIdx.x] += t;
        __syncthreads();
    }
    if (i < N_NODES) row_start[i] = s[threadIdx.x] - v;
    if (threadIdx.x == SCAN_BLK - 1) block_sums[blockIdx.x] = s[threadIdx.x];
}

__global__ __launch_bounds__(256) void scan_finish_kernel(int E, int nb) {
    __shared__ int s[256];
    __shared__ int excl[256];
    int v = (threadIdx.x < nb) ? block_sums[threadIdx.x] : 0;
    s[threadIdx.x] = v;
    __syncthreads();
#pragma unroll
    for (int off = 1; off < 256; off <<= 1) {
        int t = (threadIdx.x >= off) ? s[threadIdx.x - off] : 0;
        __syncthreads();
        s[threadIdx.x] += t;
        __syncthreads();
    }
    excl[threadIdx.x] = s[threadIdx.x] - v;
    __syncthreads();

    int i = blockIdx.x * blockDim.x + threadIdx.x;
    if (i < N_NODES) {
        int r = row_start[i] + excl[i / SCAN_BLK];
        row_start[i] = r;
        cursor_buf[i] = r;
        dinv_buf[i] = rsqrtf((float)cnt_buf[i] + 1.0f);  // deg + self loop
        cnt_buf[i] = 0;
    }
    if (i == 0) row_start[N_NODES] = E;
}

__global__ void place_kernel(const int* __restrict__ ei, int E) {
    int e = blockIdx.x * blockDim.x + threadIdx.x;
    if (e < E) {
        int s = ei[e];
        int d = ei[E + e];
        int pos = atomicAdd(&cursor_buf[d], 1);
        csr_src[pos] = s;
    }
}

// ---------------------------------------------------------------------------
// GEMM: g[row] = (x[row] @ W^T) * dinv[row]. (r12 conflict-free + FFMA2)
// ---------------------------------------------------------------------------
__global__ __launch_bounds__(256) void gemm_scale_kernel(
    const float* __restrict__ x, const float* __restrict__ W) {
    __shared__ __align__(16) float Wt[64 * KSTRIDE];  // [k][j], swizzled
    __shared__ __align__(16) float Xt[64 * KSTRIDE];  // [k][r], swizzled

    int tid = threadIdx.x;
    int rowBase = blockIdx.x * 64;

    const float4* W4 = (const float4*)W;
    const float4* x4 = (const float4*)x;
    for (int i = tid; i < 1024; i += 256) {
        int j = i >> 4;
        int kk = i & 15;
        int j4 = j >> 2, jr = j & 3;
        float4 w = W4[i];
#pragma unroll
        for (int c = 0; c < 4; c++) {
            int k = 4 * kk + c;
            int col = ((j4 ^ (kk & 7)) << 2) + jr;
            float wv = (c == 0) ? w.x : (c == 1) ? w.y : (c == 2) ? w.z : w.w;
            Wt[k * KSTRIDE + col] = wv;
        }
        float4 xv = make_float4(0.f, 0.f, 0.f, 0.f);
        if (rowBase + j < N_NODES) xv = x4[(size_t)(rowBase + j) * 16 + kk];
#pragma unroll
        for (int c = 0; c < 4; c++) {
            int k = 4 * kk + c;
            int col = ((j4 ^ (kk & 7)) << 2) + jr;
            float vv = (c == 0) ? xv.x : (c == 1) ? xv.y : (c == 2) ? xv.z : xv.w;
            Xt[k * KSTRIDE + col] = vv;
        }
    }
    __syncthreads();

    int tx = tid & 15;
    int ty = tid >> 4;

    unsigned long long acc2[4][2];
#pragma unroll
    for (int i = 0; i < 4; i++) { acc2[i][0] = 0ULL; acc2[i][1] = 0ULL; }

#pragma unroll
    for (int k = 0; k < 64; k++) {
        int f = (k >> 2) & 7;
        const ulonglong2 wv2 =
            *(const ulonglong2*)&Wt[k * KSTRIDE + ((tx ^ f) << 2)];
        const float4 xv = *(const float4*)&Xt[k * KSTRIDE + ((ty ^ f) << 2)];
        float xr[4] = {xv.x, xv.y, xv.z, xv.w};
#pragma unroll
        for (int i = 0; i < 4; i++) {
            unsigned long long xx = pack2(xr[i], xr[i]);
            ffma2(acc2[i][0], xx, wv2.x);
            ffma2(acc2[i][1], xx, wv2.y);
        }
    }

#pragma unroll
    for (int i = 0; i < 4; i++) {
        int row = rowBase + ty * 4 + i;
        if (row < N_NODES) {
            float di = dinv_buf[row];
            float o0, o1, o2, o3;
            unpack2(acc2[i][0], o0, o1);
            unpack2(acc2[i][1], o2, o3);
            float4 v;
            v.x = o0 * di;
            v.y = o1 * di;
            v.z = o2 * di;
            v.w = o3 * di;
            ((float4*)g_buf)[(size_t)row * 16 + tx] = v;
        }
    }
}

// ---------------------------------------------------------------------------
// Pull + fused finalize — SOFTWARE-PIPELINED.
// 16 threads per dst node (one float4 each). The index fetch is rotated one
// iteration ahead of the gathers, so the idx->gather two-hop dependency
// never serializes: each loop iteration issues 4 next-index loads AND
// 4 gathers whose indices are already in registers. MLP per node = 4 rows.
// ---------------------------------------------------------------------------
__global__ __launch_bounds__(256) void pull_kernel(
    const float* __restrict__ b, float* __restrict__ out) {
    int gid = blockIdx.x * blockDim.x + threadIdx.x;
    int node = gid >> 4;
    if (node >= N_NODES) return;
    int q = gid & 15;

    const float4* g4 = (const float4*)g_buf;
    int beg = row_start[node];
    int end = row_start[node + 1];

    float4 acc = g4[(size_t)node * 16 + q];  // self loop

    int n4 = (end - beg) & ~3;  // edges handled by the pipelined loop
    if (n4 > 0) {
        int s0 = csr_src[beg];
        int s1 = csr_src[beg + 1];
        int s2 = csr_src[beg + 2];
        int s3 = csr_src[beg + 3];
#pragma unroll 1
        for (int e = beg + 4; e < beg + n4; e += 4) {
            // next indices first: independent, issue immediately
            int t0 = csr_src[e];
            int t1 = csr_src[e + 1];
            int t2 = csr_src[e + 2];
            int t3 = csr_src[e + 3];
            // gathers on already-resident indices: 4 independent LDG.128
            float4 v0 = g4[(size_t)s0 * 16 + q];
            float4 v1 = g4[(size_t)s1 * 16 + q];
            float4 v2 = g4[(size_t)s2 * 16 + q];
            float4 v3 = g4[(size_t)s3 * 16 + q];
            acc.x += (v0.x + v1.x) + (v2.x + v3.x);
            acc.y += (v0.y + v1.y) + (v2.y + v3.y);
            acc.z += (v0.z + v1.z) + (v2.z + v3.z);
            acc.w += (v0.w + v1.w) + (v2.w + v3.w);
            s0 = t0; s1 = t1; s2 = t2; s3 = t3;
        }
        // drain the last pipelined batch
        float4 v0 = g4[(size_t)s0 * 16 + q];
        float4 v1 = g4[(size_t)s1 * 16 + q];
        float4 v2 = g4[(size_t)s2 * 16 + q];
        float4 v3 = g4[(size_t)s3 * 16 + q];
        acc.x += (v0.x + v1.x) + (v2.x + v3.x);
        acc.y += (v0.y + v1.y) + (v2.y + v3.y);
        acc.z += (v0.z + v1.z) + (v2.z + v3.z);
        acc.w += (v0.w + v1.w) + (v2.w + v3.w);
    }
    // remainder (<= 3 edges)
    for (int e = beg + n4; e < end; e++) {
        int s = csr_src[e];
        float4 v = g4[(size_t)s * 16 + q];
        acc.x += v.x;
        acc.y += v.y;
        acc.z += v.z;
        acc.w += v.w;
    }

    float di = dinv_buf[node];
    float4 bb = ((const float4*)b)[q];
    float4 o;
    o.x = fmaf(di, acc.x, bb.x);
    o.y = fmaf(di, acc.y, bb.y);
    o.z = fmaf(di, acc.z, bb.z);
    o.w = fmaf(di, acc.w, bb.w);
    ((float4*)out)[gid] = o;
}

// ---------------------------------------------------------------------------
extern "C" void kernel_launch(void* const* d_in, const int* in_sizes, int n_in,
                              void* d_out, int out_size) {
    const float* x = (const float*)d_in[0];
    const int* ei = (const int*)d_in[1];
    const float* W1 = (const float*)d_in[2];
    const float* b1 = (const float*)d_in[3];
    const float* W2 = (const float*)d_in[4];
    const float* b2 = (const float*)d_in[5];
    float* out = (float*)d_out;

    int E = in_sizes[1] / 2;

    int nThreads = 256;
    int nodeBlocks = (N_NODES + nThreads - 1) / nThreads;
    int edgeBlocks = (E + nThreads - 1) / nThreads;
    int gemmBlocks = (N_NODES + 63) / 64;
    int pullBlocks = (N_NODES * 16 + nThreads - 1) / nThreads;
    int scanBlocks = (N_NODES + SCAN_BLK - 1) / SCAN_BLK;

    hist_kernel<<<edgeBlocks, nThreads>>>(ei, E);                 // 1
    scan_block_kernel<<<scanBlocks, SCAN_BLK>>>();                // 2
    scan_finish_kernel<<<nodeBlocks, nThreads>>>(E, scanBlocks);  // 3
    gemm_scale_kernel<<<gemmBlocks, nThreads>>>(x, W1);           // 4 <-- ncu window
    place_kernel<<<edgeBlocks, nThreads>>>(ei, E);                // 5

    // Layer 1 aggregation
    pull_kernel<<<pullBlocks, nThreads>>>(b1, h1_buf);            // 6

    // Layer 2
    gemm_scale_kernel<<<gemmBlocks, nThreads>>>(h1_buf, W2);      // 7
    pull_kernel<<<pullBlocks, nThreads>>>(b2, out);               // 8
}

// round 15
// speedup vs baseline: 1.2858x; 1.0251x over previous
#include <cuda_runtime.h>
#include <cuda_fp16.h>
#include <cstdint>

#define N_NODES 100000
#define D 64
#define E_MAX 1700000
#define SCAN_BLK 512
#define KSTRIDE 68  // floats per k-row in smem; 68*4=272B, 16B-aligned

// Scratch (__device__ globals: the sanctioned allocation-free path).
// g stored as fp16: halves pull gather traffic and fits L2 next to csr.
__device__ __align__(16) __half g_h[N_NODES * D];    // g = (x @ W^T) * dinv[row], fp16
__device__ __align__(16) float h1_buf[N_NODES * D];  // layer-1 output (fp32)
__device__ float dinv_buf[N_NODES];
__device__ int cnt_buf[N_NODES];       // in-degree histogram (re-zeroed by scan_finish)
__device__ int row_start[N_NODES + 1]; // CSR row offsets (by dst)
__device__ int cursor_buf[N_NODES];    // placement cursors
__device__ int csr_src[E_MAX];         // CSR column (src) indices
__device__ int block_sums[(N_NODES + SCAN_BLK - 1) / SCAN_BLK];

// f32x2 packed helpers (Blackwell FFMA2 path — PTX only)
__device__ __forceinline__ void ffma2(unsigned long long& acc,
                                      unsigned long long a, unsigned long long b) {
    asm("fma.rn.f32x2 %0, %1, %2, %3;" : "=l"(acc) : "l"(a), "l"(b), "l"(acc));
}
__device__ __forceinline__ unsigned long long pack2(float lo, float hi) {
    unsigned long long r;
    asm("mov.b64 %0, {%1, %2};" : "=l"(r) : "f"(lo), "f"(hi));
    return r;
}
__device__ __forceinline__ void unpack2(unsigned long long v, float& lo, float& hi) {
    asm("mov.b64 {%0, %1}, %2;" : "=f"(lo), "=f"(hi) : "l"(v));
}

// ---------------------------------------------------------------------------
// Histogram of in-degrees. cnt_buf zero on entry (.bss call 1, re-zeroed
// by scan_finish each call). Edge buffer is int32 (proven in rounds 3/4).
// ---------------------------------------------------------------------------
__global__ void hist_kernel(const int* __restrict__ ei, int E) {
    int e = blockIdx.x * blockDim.x + threadIdx.x;
    if (e < E) atomicAdd(&cnt_buf[ei[E + e]], 1);
}

__global__ __launch_bounds__(SCAN_BLK) void scan_block_kernel() {
    __shared__ int s[SCAN_BLK];
    int i = blockIdx.x * SCAN_BLK + threadIdx.x;
    int v = (i < N_NODES) ? cnt_buf[i] : 0;
    s[threadIdx.x] = v;
    __syncthreads();
#pragma unroll
    for (int off = 1; off < SCAN_BLK; off <<= 1) {
        int t = (threadIdx.x >= off) ? s[threadIdx.x - off] : 0;
        __syncthreads();
        s[threadIdx.x] += t;
        __syncthreads();
    }
    if (i < N_NODES) row_start[i] = s[threadIdx.x] - v;
    if (threadIdx.x == SCAN_BLK - 1) block_sums[blockIdx.x] = s[threadIdx.x];
}

__global__ __launch_bounds__(256) void scan_finish_kernel(int E, int nb) {
    __shared__ int s[256];
    __shared__ int excl[256];
    int v = (threadIdx.x < nb) ? block_sums[threadIdx.x] : 0;
    s[threadIdx.x] = v;
    __syncthreads();
#pragma unroll
    for (int off = 1; off < 256; off <<= 1) {
        int t = (threadIdx.x >= off) ? s[threadIdx.x - off] : 0;
        __syncthreads();
        s[threadIdx.x] += t;
        __syncthreads();
    }
    excl[threadIdx.x] = s[threadIdx.x] - v;
    __syncthreads();

    int i = blockIdx.x * blockDim.x + threadIdx.x;
    if (i < N_NODES) {
        int r = row_start[i] + excl[i / SCAN_BLK];
        row_start[i] = r;
        cursor_buf[i] = r;
        dinv_buf[i] = rsqrtf((float)cnt_buf[i] + 1.0f);  // deg + self loop
        cnt_buf[i] = 0;
    }
    if (i == 0) row_start[N_NODES] = E;
}

__global__ void place_kernel(const int* __restrict__ ei, int E) {
    int e = blockIdx.x * blockDim.x + threadIdx.x;
    if (e < E) {
        int s = ei[e];
        int d = ei[E + e];
        int pos = atomicAdd(&cursor_buf[d], 1);
        csr_src[pos] = s;
    }
}

// ---------------------------------------------------------------------------
// GEMM: g[row] = (x[row] @ W^T) * dinv[row], stored as fp16.
// (r12 conflict-free smem layout + FFMA2 inner loop.)
// ---------------------------------------------------------------------------
__global__ __launch_bounds__(256) void gemm_scale_kernel(
    const float* __restrict__ x, const float* __restrict__ W) {
    __shared__ __align__(16) float Wt[64 * KSTRIDE];  // [k][j], swizzled
    __shared__ __align__(16) float Xt[64 * KSTRIDE];  // [k][r], swizzled

    int tid = threadIdx.x;
    int rowBase = blockIdx.x * 64;

    const float4* W4 = (const float4*)W;
    const float4* x4 = (const float4*)x;
    for (int i = tid; i < 1024; i += 256) {
        int j = i >> 4;
        int kk = i & 15;
        int j4 = j >> 2, jr = j & 3;
        float4 w = W4[i];
#pragma unroll
        for (int c = 0; c < 4; c++) {
            int k = 4 * kk + c;
            int col = ((j4 ^ (kk & 7)) << 2) + jr;
            float wv = (c == 0) ? w.x : (c == 1) ? w.y : (c == 2) ? w.z : w.w;
            Wt[k * KSTRIDE + col] = wv;
        }
        float4 xv = make_float4(0.f, 0.f, 0.f, 0.f);
        if (rowBase + j < N_NODES) xv = x4[(size_t)(rowBase + j) * 16 + kk];
#pragma unroll
        for (int c = 0; c < 4; c++) {
            int k = 4 * kk + c;
            int col = ((j4 ^ (kk & 7)) << 2) + jr;
            float vv = (c == 0) ? xv.x : (c == 1) ? xv.y : (c == 2) ? xv.z : xv.w;
            Xt[k * KSTRIDE + col] = vv;
        }
    }
    __syncthreads();

    int tx = tid & 15;
    int ty = tid >> 4;

    unsigned long long acc2[4][2];
#pragma unroll
    for (int i = 0; i < 4; i++) { acc2[i][0] = 0ULL; acc2[i][1] = 0ULL; }

#pragma unroll
    for (int k = 0; k < 64; k++) {
        int f = (k >> 2) & 7;
        const ulonglong2 wv2 =
            *(const ulonglong2*)&Wt[k * KSTRIDE + ((tx ^ f) << 2)];
        const float4 xv = *(const float4*)&Xt[k * KSTRIDE + ((ty ^ f) << 2)];
        float xr[4] = {xv.x, xv.y, xv.z, xv.w};
#pragma unroll
        for (int i = 0; i < 4; i++) {
            unsigned long long xx = pack2(xr[i], xr[i]);
            ffma2(acc2[i][0], xx, wv2.x);
            ffma2(acc2[i][1], xx, wv2.y);
        }
    }

#pragma unroll
    for (int i = 0; i < 4; i++) {
        int row = rowBase + ty * 4 + i;
        if (row < N_NODES) {
            float di = dinv_buf[row];
            float o0, o1, o2, o3;
            unpack2(acc2[i][0], o0, o1);
            unpack2(acc2[i][1], o2, o3);
            __half2 h01 = __floats2half2_rn(o0 * di, o1 * di);
            __half2 h23 = __floats2half2_rn(o2 * di, o3 * di);
            uint2 pk;
            pk.x = *(unsigned int*)&h01;
            pk.y = *(unsigned int*)&h23;
            // row stride = 64 halves = 16 uint2; lane tx owns halves 4tx..4tx+3
            ((uint2*)g_h)[(size_t)row * 16 + tx] = pk;
        }
    }
}

// ---------------------------------------------------------------------------
// Pull + fused finalize, fp16 gathers (8B/lane, 128B/edge), fp32 accumulate.
// 16 threads per dst node; lane q owns cols 4q..4q+3.
// Index fetch software-pipelined one batch ahead (kept from r13).
// ---------------------------------------------------------------------------
__device__ __forceinline__ void acc_row(float4& acc, uint2 pk) {
    __half2 h01 = *(__half2*)&pk.x;
    __half2 h23 = *(__half2*)&pk.y;
    float2 f01 = __half22float2(h01);
    float2 f23 = __half22float2(h23);
    acc.x += f01.x;
    acc.y += f01.y;
    acc.z += f23.x;
    acc.w += f23.y;
}

__global__ __launch_bounds__(256) void pull_kernel(
    const float* __restrict__ b, float* __restrict__ out) {
    int gid = blockIdx.x * blockDim.x + threadIdx.x;
    int node = gid >> 4;
    if (node >= N_NODES) return;
    int q = gid & 15;

    const uint2* g2 = (const uint2*)g_h;
    int beg = row_start[node];
    int end = row_start[node + 1];

    float4 acc = make_float4(0.f, 0.f, 0.f, 0.f);
    acc_row(acc, g2[(size_t)node * 16 + q]);  // self loop

    int n4 = (end - beg) & ~3;
    if (n4 > 0) {
        int s0 = csr_src[beg];
        int s1 = csr_src[beg + 1];
        int s2 = csr_src[beg + 2];
        int s3 = csr_src[beg + 3];
#pragma unroll 1
        for (int e = beg + 4; e < beg + n4; e += 4) {
            int t0 = csr_src[e];
            int t1 = csr_src[e + 1];
            int t2 = csr_src[e + 2];
            int t3 = csr_src[e + 3];
            uint2 v0 = g2[(size_t)s0 * 16 + q];
            uint2 v1 = g2[(size_t)s1 * 16 + q];
            uint2 v2 = g2[(size_t)s2 * 16 + q];
            uint2 v3 = g2[(size_t)s3 * 16 + q];
            acc_row(acc, v0);
            acc_row(acc, v1);
            acc_row(acc, v2);
            acc_row(acc, v3);
            s0 = t0; s1 = t1; s2 = t2; s3 = t3;
        }
        uint2 v0 = g2[(size_t)s0 * 16 + q];
        uint2 v1 = g2[(size_t)s1 * 16 + q];
        uint2 v2 = g2[(size_t)s2 * 16 + q];
        uint2 v3 = g2[(size_t)s3 * 16 + q];
        acc_row(acc, v0);
        acc_row(acc, v1);
        acc_row(acc, v2);
        acc_row(acc, v3);
    }
    for (int e = beg + n4; e < end; e++) {
        int s = csr_src[e];
        acc_row(acc, g2[(size_t)s * 16 + q]);
    }

    float di = dinv_buf[node];
    float4 bb = ((const float4*)b)[q];
    float4 o;
    o.x = fmaf(di, acc.x, bb.x);
    o.y = fmaf(di, acc.y, bb.y);
    o.z = fmaf(di, acc.z, bb.z);
    o.w = fmaf(di, acc.w, bb.w);
    ((float4*)out)[gid] = o;
}

// ---------------------------------------------------------------------------
extern "C" void kernel_launch(void* const* d_in, const int* in_sizes, int n_in,
                              void* d_out, int out_size) {
    const float* x = (const float*)d_in[0];
    const int* ei = (const int*)d_in[1];
    const float* W1 = (const float*)d_in[2];
    const float* b1 = (const float*)d_in[3];
    const float* W2 = (const float*)d_in[4];
    const float* b2 = (const float*)d_in[5];
    float* out = (float*)d_out;

    int E = in_sizes[1] / 2;

    int nThreads = 256;
    int nodeBlocks = (N_NODES + nThreads - 1) / nThreads;
    int edgeBlocks = (E + nThreads - 1) / nThreads;
    int gemmBlocks = (N_NODES + 63) / 64;
    int pullBlocks = (N_NODES * 16 + nThreads - 1) / nThreads;
    int scanBlocks = (N_NODES + SCAN_BLK - 1) / SCAN_BLK;

    hist_kernel<<<edgeBlocks, nThreads>>>(ei, E);                 // 1
    scan_block_kernel<<<scanBlocks, SCAN_BLK>>>();                // 2
    scan_finish_kernel<<<nodeBlocks, nThreads>>>(E, scanBlocks);  // 3
    gemm_scale_kernel<<<gemmBlocks, nThreads>>>(x, W1);           // 4 <-- ncu window
    place_kernel<<<edgeBlocks, nThreads>>>(ei, E);                // 5

    // Layer 1 aggregation
    pull_kernel<<<pullBlocks, nThreads>>>(b1, h1_buf);            // 6

    // Layer 2
    gemm_scale_kernel<<<gemmBlocks, nThreads>>>(h1_buf, W2);      // 7
    pull_kernel<<<pullBlocks, nThreads>>>(b2, out);               // 8
}